// round 2
// baseline (speedup 1.0000x reference)
#include <cuda_runtime.h>
#include <cstdint>

// FeatureAGCNStyle fused kernel: 2-layer adaptive GCN + classifier, TF32 MMA.
// One CTA processes BATCH=4 samples; all intermediates stay in shared memory.

#define THREADS 384
#define NWARPS  12
#define BATCH   4
#define LD0     68     // stride (floats) for K=64 buffers (x, h0, W0, W1)
#define LD1     132    // stride (floats) for K=128 buffers (h1, W2 chunk)

// shared-memory float offsets
#define OFF_B0   0
#define OFF_G0   64
#define OFF_BE0  112
#define OFF_B1   160
#define OFF_G1   288
#define OFF_BE1  336
#define OFF_B2   384
#define OFF_G2   640
#define OFF_BE2  688
#define OFF_ADJ1 768
#define OFF_ADJ2 (768 + 2304)
#define OFF_H1   5376              // 192*132 = 25344 ; also W0 staging during stage0
#define OFF_W0   5376
#define OFF_BUFA 30720             // 192*68 = 13056 : x -> W1 -> W2 chunk
#define OFF_BUFB 43776             // 192*68 = 13056 : h0 -> feat
#define OFF_FEAT 43776
#define SMEM_FLOATS 56832
#define SMEM_BYTES  (SMEM_FLOATS * 4)

__device__ __constant__ int c_EU[23] = {0,1,2,3,0,5,6,7,0,9,10,11,0,13,14,15,0,17,18,19,5,9,13};
__device__ __constant__ int c_EV[23] = {1,2,3,4,5,6,7,8,9,10,11,12,13,14,15,16,17,18,19,20,9,13,17};

__device__ __forceinline__ float tf32r(float x) {
    uint32_t r;
    asm("cvt.rna.tf32.f32 %0, %1;" : "=r"(r) : "f"(x));
    return __uint_as_float(r);
}
__device__ __forceinline__ uint32_t fu(float x) { return __float_as_uint(x); }

__device__ __forceinline__ void mma8(float c[4], const uint32_t a[4], const uint32_t b[2]) {
    asm volatile(
        "mma.sync.aligned.m16n8k8.row.col.f32.tf32.tf32.f32 "
        "{%0,%1,%2,%3},{%4,%5,%6,%7},{%8,%9},{%0,%1,%2,%3};\n"
        : "+f"(c[0]), "+f"(c[1]), "+f"(c[2]), "+f"(c[3])
        : "r"(a[0]), "r"(a[1]), "r"(a[2]), "r"(a[3]), "r"(b[0]), "r"(b[1]));
}

// 2m x 4n register-blocked GEMM group: rows from A (row-major, LDA), weights B[n][k] (LDB).
template <int K, int LDA, int LDB>
__device__ __forceinline__ void gemm_group(const float* sm, int aoff, int boff,
                                           int m0, int n0, int lr, int lc,
                                           float acc[2][4][4]) {
#pragma unroll
    for (int im = 0; im < 2; im++)
#pragma unroll
        for (int in = 0; in < 4; in++)
#pragma unroll
            for (int q = 0; q < 4; q++) acc[im][in][q] = 0.f;

#pragma unroll
    for (int k0 = 0; k0 < K; k0 += 8) {
        uint32_t A[2][4], Bf[4][2];
#pragma unroll
        for (int im = 0; im < 2; im++) {
            const float* ap = sm + aoff + (m0 + im * 16 + lr) * LDA + k0 + lc;
            A[im][0] = fu(ap[0]);
            A[im][1] = fu(ap[8 * LDA]);
            A[im][2] = fu(ap[4]);
            A[im][3] = fu(ap[8 * LDA + 4]);
        }
#pragma unroll
        for (int in = 0; in < 4; in++) {
            const float* bp = sm + boff + (n0 + in * 8 + lr) * LDB + k0 + lc;
            Bf[in][0] = fu(bp[0]);
            Bf[in][1] = fu(bp[4]);
        }
#pragma unroll
        for (int im = 0; im < 2; im++)
#pragma unroll
            for (int in = 0; in < 4; in++) mma8(acc[im][in], A[im], Bf[in]);
    }
}

// In-place graph aggregation: h[s] <- adj(48x48) @ h[s], per 8-column strip per warp.
// Column strips are disjoint across warps -> no temp buffer, no intra-phase sync.
template <int C, int LDH>
__device__ __forceinline__ void agg_inplace(float* sm, int offH, int offAdj,
                                            int wid, int lr, int lc) {
    uint32_t Af[3][6][4];
#pragma unroll
    for (int mi = 0; mi < 3; mi++)
#pragma unroll
        for (int ks = 0; ks < 6; ks++) {
            const float* ap = sm + offAdj + (mi * 16 + lr) * 48 + ks * 8 + lc;
            Af[mi][ks][0] = fu(ap[0]);
            Af[mi][ks][1] = fu(ap[8 * 48]);
            Af[mi][ks][2] = fu(ap[4]);
            Af[mi][ks][3] = fu(ap[8 * 48 + 4]);
        }
    const int NS = BATCH * (C / 8);
    for (int st = wid; st < NS; st += NWARPS) {
        int s = st / (C / 8);
        int n0 = (st % (C / 8)) * 8;
        int base = s * 48;
        float acc[3][4] = {};
#pragma unroll
        for (int ks = 0; ks < 6; ks++) {
            uint32_t Bf[2];
            const float* bp = sm + offH + (base + ks * 8 + lc) * LDH + n0 + lr;
            Bf[0] = fu(bp[0]);
            Bf[1] = fu(bp[4 * LDH]);
#pragma unroll
            for (int mi = 0; mi < 3; mi++) mma8(acc[mi], Af[mi][ks], Bf);
        }
#pragma unroll
        for (int mi = 0; mi < 3; mi++) {
            float* op = sm + offH + (base + mi * 16 + lr) * LDH + n0 + 2 * lc;
            op[0] = tf32r(acc[mi][0]);
            op[1] = tf32r(acc[mi][1]);
            op[8 * LDH] = tf32r(acc[mi][2]);
            op[8 * LDH + 1] = tf32r(acc[mi][3]);
        }
    }
}

__global__ __launch_bounds__(THREADS, 1)
void agcn_fused(const float* __restrict__ x,
                const float* __restrict__ W0, const float* __restrict__ b0,
                const float* __restrict__ g0, const float* __restrict__ be0,
                const float* __restrict__ W1, const float* __restrict__ b1,
                const float* __restrict__ Badj1, const float* __restrict__ g1,
                const float* __restrict__ be1,
                const float* __restrict__ W2, const float* __restrict__ b2,
                const float* __restrict__ Badj2, const float* __restrict__ g2,
                const float* __restrict__ be2,
                const float* __restrict__ Wc, const float* __restrict__ bc,
                float* __restrict__ out, int Ntot) {
    extern __shared__ float sm[];
    const int t = threadIdx.x;
    const int wid = t >> 5, lane = t & 31, lr = lane >> 2, lc = lane & 3;
    const int n0g = blockIdx.x * BATCH;
    const float bnscale = rsqrtf(1.0f + 1e-5f);

    // ---- Phase A: stage BN/bias params; zero adjacency region ----
    for (int i = t; i < 64; i += THREADS) sm[OFF_B0 + i] = b0[i];
    for (int i = t; i < 128; i += THREADS) sm[OFF_B1 + i] = b1[i];
    for (int i = t; i < 256; i += THREADS) sm[OFF_B2 + i] = b2[i];
    for (int i = t; i < 48; i += THREADS) {
        bool ok = i < 42;
        sm[OFF_G0 + i]  = ok ? g0[i] * bnscale : 0.f;
        sm[OFF_BE0 + i] = ok ? be0[i] : 0.f;
        sm[OFF_G1 + i]  = ok ? g1[i] * bnscale : 0.f;
        sm[OFF_BE1 + i] = ok ? be1[i] : 0.f;
        sm[OFF_G2 + i]  = ok ? g2[i] * bnscale : 0.f;
        sm[OFF_BE2 + i] = ok ? be2[i] : 0.f;
    }
    for (int i = t; i < 2 * 48 * 48; i += THREADS) sm[OFF_ADJ1 + i] = 0.f;
    __syncthreads();

    // ---- Phase B: build softmax adjacencies; load x tile; stage W0 ----
    if (t < 96) {
        int mat = t / 48, v = t % 48;
        if (v < 42) {
            const float* Bm = mat ? Badj2 : Badj1;
            float* arow = sm + (mat ? OFF_ADJ2 : OFF_ADJ1) + v * 48;
            int hand = v / 21, lv = v % 21;
            unsigned mask = 0;
#pragma unroll
            for (int e = 0; e < 23; e++) {
                if (c_EU[e] == lv) mask |= 1u << c_EV[e];
                if (c_EV[e] == lv) mask |= 1u << c_EU[e];
            }
            float deg = (float)(__popc(mask) + 1 + ((v == 0 || v == 21) ? 1 : 0));
            float inv = 1.0f / deg;
            float mx = -1e30f;
            for (int u = 0; u < 42; u++) {
                float bse = 0.f;
                if (u == v) bse += 1.f;
                if (u / 21 == hand && ((mask >> (u % 21)) & 1u)) bse += 1.f;
                if ((v == 0 && u == 21) || (v == 21 && u == 0)) bse += 1.f;
                float val = bse * inv + Bm[v * 42 + u];
                arow[u] = val;
                mx = fmaxf(mx, val);
            }
            float ssum = 0.f;
            for (int u = 0; u < 42; u++) {
                float e = expf(arow[u] - mx);
                arow[u] = e;
                ssum += e;
            }
            float is = 1.0f / ssum;
            for (int u = 0; u < 42; u++) arow[u] = tf32r(arow[u] * is);
        }
    }
    {   // x tile: (4 samples, 42 joints, 64 feats) -> rows s*48+j, stride 68, tf32-rounded
        const float4* x4 = reinterpret_cast<const float4*>(x) + (size_t)n0g * 672;
        for (int i = t; i < BATCH * 672; i += THREADS) {
            int s = i / 672, r4 = i - s * 672;
            float4 vv = make_float4(0.f, 0.f, 0.f, 0.f);
            if (n0g + s < Ntot) vv = x4[i];
            int j = r4 >> 4, c = (r4 & 15) << 2;
            float* dst = sm + OFF_BUFA + (s * 48 + j) * LD0 + c;
            dst[0] = tf32r(vv.x); dst[1] = tf32r(vv.y);
            dst[2] = tf32r(vv.z); dst[3] = tf32r(vv.w);
        }
        for (int i = t; i < BATCH * 6 * 64; i += THREADS) {  // zero padded joint rows
            int s = i / 384, rr = i - s * 384;
            sm[OFF_BUFA + (s * 48 + 42 + rr / 64) * LD0 + (rr & 63)] = 0.f;
        }
    }
    for (int i = t; i < 64 * 64; i += THREADS)
        sm[OFF_W0 + (i >> 6) * LD0 + (i & 63)] = tf32r(W0[i]);
    __syncthreads();

    // ---- Phase C: stage0  h0 = relu(bn(x @ W0^T + b0)) ----
    for (int g = wid; g < 12; g += NWARPS) {
        int mi2 = g % 6, nq = g / 6, m0 = mi2 * 32, n0 = nq * 32;
        float acc[2][4][4];
        gemm_group<64, LD0, LD0>(sm, OFF_BUFA, OFF_W0, m0, n0, lr, lc, acc);
#pragma unroll
        for (int im = 0; im < 2; im++) {
            int r = m0 + im * 16 + lr;
            int v = r % 48, v8 = v + 8;
            float s0 = (v < 42) ? sm[OFF_G0 + v] : 0.f;
            float be = (v < 42) ? sm[OFF_BE0 + v] : 0.f;
            float s8 = (v8 < 42) ? sm[OFF_G0 + v8] : 0.f;
            float be8 = (v8 < 42) ? sm[OFF_BE0 + v8] : 0.f;
#pragma unroll
            for (int in = 0; in < 4; in++) {
                int c0 = n0 + in * 8 + 2 * lc;
                float bb0 = sm[OFF_B0 + c0], bb1 = sm[OFF_B0 + c0 + 1];
                float* hp = sm + OFF_BUFB + r * LD0 + c0;
                hp[0] = tf32r((v < 42) ? fmaxf((acc[im][in][0] + bb0) * s0 + be, 0.f) : 0.f);
                hp[1] = tf32r((v < 42) ? fmaxf((acc[im][in][1] + bb1) * s0 + be, 0.f) : 0.f);
                hp[8 * LD0] = tf32r((v8 < 42) ? fmaxf((acc[im][in][2] + bb0) * s8 + be8, 0.f) : 0.f);
                hp[8 * LD0 + 1] = tf32r((v8 < 42) ? fmaxf((acc[im][in][3] + bb1) * s8 + be8, 0.f) : 0.f);
            }
        }
    }
    __syncthreads();

    // ---- Phase D: stage W1 (into freed x buffer) + agg1 in-place on h0 ----
    for (int i = t; i < 128 * 64; i += THREADS)
        sm[OFF_BUFA + (i >> 6) * LD0 + (i & 63)] = tf32r(W1[i]);
    agg_inplace<64, LD0>(sm, OFF_BUFB, OFF_ADJ1, wid, lr, lc);
    __syncthreads();

    // ---- Phase E: lin1  h1 = relu(bn(agg1 @ W1^T + b1)) ----
    for (int g = wid; g < 24; g += NWARPS) {
        int mi2 = g % 6, nq = g / 6, m0 = mi2 * 32, n0 = nq * 32;
        float acc[2][4][4];
        gemm_group<64, LD0, LD0>(sm, OFF_BUFB, OFF_BUFA, m0, n0, lr, lc, acc);
#pragma unroll
        for (int im = 0; im < 2; im++) {
            int r = m0 + im * 16 + lr;
            int v = r % 48, v8 = v + 8;
            float s0 = (v < 42) ? sm[OFF_G1 + v] : 0.f;
            float be = (v < 42) ? sm[OFF_BE1 + v] : 0.f;
            float s8 = (v8 < 42) ? sm[OFF_G1 + v8] : 0.f;
            float be8 = (v8 < 42) ? sm[OFF_BE1 + v8] : 0.f;
#pragma unroll
            for (int in = 0; in < 4; in++) {
                int c0 = n0 + in * 8 + 2 * lc;
                float bb0 = sm[OFF_B1 + c0], bb1 = sm[OFF_B1 + c0 + 1];
                float* hp = sm + OFF_H1 + r * LD1 + c0;
                hp[0] = tf32r((v < 42) ? fmaxf((acc[im][in][0] + bb0) * s0 + be, 0.f) : 0.f);
                hp[1] = tf32r((v < 42) ? fmaxf((acc[im][in][1] + bb1) * s0 + be, 0.f) : 0.f);
                hp[8 * LD1] = tf32r((v8 < 42) ? fmaxf((acc[im][in][2] + bb0) * s8 + be8, 0.f) : 0.f);
                hp[8 * LD1 + 1] = tf32r((v8 < 42) ? fmaxf((acc[im][in][3] + bb1) * s8 + be8, 0.f) : 0.f);
            }
        }
    }
    __syncthreads();

    // ---- Phase F: agg2 in-place on h1 + zero feat ----
    agg_inplace<128, LD1>(sm, OFF_H1, OFF_ADJ2, wid, lr, lc);
    for (int i = t; i < BATCH * 256; i += THREADS) sm[OFF_FEAT + i] = 0.f;
    __syncthreads();

    // ---- Phase G: lin2 (chunked over 256 out-channels) fused with joint-mean ----
    for (int ch = 0; ch < 4; ch++) {
        for (int i = t; i < 64 * 128; i += THREADS)
            sm[OFF_BUFA + (i >> 7) * LD1 + (i & 127)] = tf32r(W2[(ch * 64 + (i >> 7)) * 128 + (i & 127)]);
        __syncthreads();
        for (int g = wid; g < 12; g += NWARPS) {
            int mi2 = g % 6, nq = g / 6, m0 = mi2 * 32, n0 = nq * 32;
            float acc[2][4][4];
            gemm_group<128, LD1, LD1>(sm, OFF_H1, OFF_BUFA, m0, n0, lr, lc, acc);
#pragma unroll
            for (int im = 0; im < 2; im++) {
                int r = m0 + im * 16 + lr;
                int v = r % 48, v8 = v + 8, s = r / 48;
#pragma unroll
                for (int in = 0; in < 4; in++) {
                    int cg = ch * 64 + n0 + in * 8 + 2 * lc;
                    float bb0 = sm[OFF_B2 + cg], bb1 = sm[OFF_B2 + cg + 1];
                    float add0 = 0.f, add1 = 0.f;
                    if (v < 42) {
                        float sc = sm[OFF_G2 + v], bb = sm[OFF_BE2 + v];
                        add0 += fmaxf((acc[im][in][0] + bb0) * sc + bb, 0.f);
                        add1 += fmaxf((acc[im][in][1] + bb1) * sc + bb, 0.f);
                    }
                    if (v8 < 42) {
                        float sc = sm[OFF_G2 + v8], bb = sm[OFF_BE2 + v8];
                        add0 += fmaxf((acc[im][in][2] + bb0) * sc + bb, 0.f);
                        add1 += fmaxf((acc[im][in][3] + bb1) * sc + bb, 0.f);
                    }
                    if (add0 != 0.f) atomicAdd(&sm[OFF_FEAT + s * 256 + cg], add0);
                    if (add1 != 0.f) atomicAdd(&sm[OFF_FEAT + s * 256 + cg + 1], add1);
                }
            }
        }
        __syncthreads();
    }

    // ---- Phase H: classifier  out = (feat/42) @ Wc^T + bc ----
    if (wid < 8) {
        int s = wid >> 1, k = wid & 1;
        const float* wc = Wc + k * 256;
        float sum = 0.f;
        for (int d = lane; d < 256; d += 32) sum += sm[OFF_FEAT + s * 256 + d] * wc[d];
#pragma unroll
        for (int o = 16; o; o >>= 1) sum += __shfl_xor_sync(0xffffffffu, sum, o);
        if (lane == 0 && n0g + s < Ntot)
            out[(n0g + s) * 2 + k] = sum * (1.0f / 42.0f) + bc[k];
    }
}

extern "C" void kernel_launch(void* const* d_in, const int* in_sizes, int n_in,
                              void* d_out, int out_size) {
    const float* x   = (const float*)d_in[0];
    const float* W0  = (const float*)d_in[1];
    const float* b0  = (const float*)d_in[2];
    const float* g0  = (const float*)d_in[3];
    const float* be0 = (const float*)d_in[4];
    const float* W1  = (const float*)d_in[5];
    const float* b1  = (const float*)d_in[6];
    const float* B1  = (const float*)d_in[7];
    const float* g1  = (const float*)d_in[8];
    const float* be1 = (const float*)d_in[9];
    const float* W2  = (const float*)d_in[10];
    const float* b2  = (const float*)d_in[11];
    const float* B2  = (const float*)d_in[12];
    const float* g2  = (const float*)d_in[13];
    const float* be2 = (const float*)d_in[14];
    const float* Wc  = (const float*)d_in[15];
    const float* bc  = (const float*)d_in[16];
    float* out = (float*)d_out;

    int Ntot = in_sizes[0] / (42 * 64);
    int grid = (Ntot + BATCH - 1) / BATCH;

    cudaFuncSetAttribute(agcn_fused, cudaFuncAttributeMaxDynamicSharedMemorySize, SMEM_BYTES);
    agcn_fused<<<grid, THREADS, SMEM_BYTES>>>(x, W0, b0, g0, be0,
                                              W1, b1, B1, g1, be1,
                                              W2, b2, B2, g2, be2,
                                              Wc, bc, out, Ntot);
}

// round 4
// speedup vs baseline: 1.6272x; 1.6272x over previous
#include <cuda_runtime.h>
#include <cuda_fp16.h>
#include <cstdint>

// FeatureAGCNStyle fused kernel, fp16 MMA (m16n8k16), f32 accumulate.
// BATCH=2 samples/CTA, 256 threads, ~70.5KB SMEM -> 3 CTAs/SM.

#define THREADS 256
#define NWARPS  8
#define BATCH   2
#define R       96     // BATCH*48 rows
#define LD0     72     // halves stride, K=64 buffers
#define LD1     136    // halves stride, K=128 buffers
#define ADJLD   48

// half-index offsets
#define HADJ1 0
#define HADJ2 2304
#define HH1   4608     // 96*136 = 13056 halves ; also W0 staging (64*72)
#define HBUFA 17664    // 9216 halves: x(96*72) -> W1(128*72) -> W2 chunk(64*136)
#define HBUFB 26880    // 6912 halves: h0(96*72) -> feat(512 floats)
#define HEND  33792
// float-index offsets (after half region: 33792 halves = 16896 floats)
#define PB0   16896
#define PB1   16960
#define PB2   17088
#define PG0   17344
#define PBE0  17392
#define PG1   17440
#define PBE1  17488
#define PG2   17536
#define PBE2  17584
#define PEND  17632
#define SMEM_BYTES (PEND * 4)

__device__ __constant__ int c_EU[23] = {0,1,2,3,0,5,6,7,0,9,10,11,0,13,14,15,0,17,18,19,5,9,13};
__device__ __constant__ int c_EV[23] = {1,2,3,4,5,6,7,8,9,10,11,12,13,14,15,16,17,18,19,20,9,13,17};

__device__ __forceinline__ uint32_t ld32h(const __half* p) { return *(const uint32_t*)p; }
__device__ __forceinline__ uint32_t pack16(const __half* p0, const __half* p1) {
    uint32_t lo = *(const uint16_t*)p0, hi = *(const uint16_t*)p1;
    return lo | (hi << 16);
}
__device__ __forceinline__ void st2(__half* p, float f0, float f1) {
    *(__half2*)p = __floats2half2_rn(f0, f1);
}

__device__ __forceinline__ void mma16(float c[4], const uint32_t a[4], const uint32_t b[2]) {
    asm volatile(
        "mma.sync.aligned.m16n8k16.row.col.f32.f16.f16.f32 "
        "{%0,%1,%2,%3},{%4,%5,%6,%7},{%8,%9},{%0,%1,%2,%3};\n"
        : "+f"(c[0]), "+f"(c[1]), "+f"(c[2]), "+f"(c[3])
        : "r"(a[0]), "r"(a[1]), "r"(a[2]), "r"(a[3]), "r"(b[0]), "r"(b[1]));
}

// 2m x 4n register-blocked fp16 GEMM: A rows (row-major halves, LDA), B = W[n][k] (LDB).
template <int KH, int LDA, int LDB>
__device__ __forceinline__ void gemm16(const __half* hs, int aoff, int boff,
                                       int m0, int n0, int lr, int lc,
                                       float acc[2][4][4]) {
#pragma unroll
    for (int im = 0; im < 2; im++)
#pragma unroll
        for (int in = 0; in < 4; in++)
#pragma unroll
            for (int q = 0; q < 4; q++) acc[im][in][q] = 0.f;

#pragma unroll
    for (int k0 = 0; k0 < KH; k0 += 16) {
        uint32_t A[2][4], B[4][2];
#pragma unroll
        for (int im = 0; im < 2; im++) {
            const __half* ap = hs + aoff + (m0 + im * 16 + lr) * LDA + k0 + 2 * lc;
            A[im][0] = ld32h(ap);
            A[im][1] = ld32h(ap + 8 * LDA);
            A[im][2] = ld32h(ap + 8);
            A[im][3] = ld32h(ap + 8 * LDA + 8);
        }
#pragma unroll
        for (int in = 0; in < 4; in++) {
            const __half* bp = hs + boff + (n0 + in * 8 + lr) * LDB + k0 + 2 * lc;
            B[in][0] = ld32h(bp);
            B[in][1] = ld32h(bp + 8);
        }
#pragma unroll
        for (int im = 0; im < 2; im++)
#pragma unroll
            for (int in = 0; in < 4; in++) mma16(acc[im][in], A[im], B[in]);
    }
}

// In-place graph aggregation h[s] <- adj(48x48) @ h[s], per 8-col strip per warp.
// adj fragments hoisted once (shared across both samples).
template <int CCH, int LDH>
__device__ __forceinline__ void agg16(__half* hs, int offH, int offAdj,
                                      int wid, int lr, int lc) {
    uint32_t Af[3][3][4];
#pragma unroll
    for (int mi = 0; mi < 3; mi++)
#pragma unroll
        for (int j = 0; j < 3; j++) {
            const __half* ap = hs + offAdj + (mi * 16 + lr) * ADJLD + j * 16 + 2 * lc;
            Af[mi][j][0] = ld32h(ap);
            Af[mi][j][1] = ld32h(ap + 8 * ADJLD);
            Af[mi][j][2] = ld32h(ap + 8);
            Af[mi][j][3] = ld32h(ap + 8 * ADJLD + 8);
        }
    const int PER = CCH / 8;
    for (int st = wid; st < BATCH * PER; st += NWARPS) {
        int s = st / PER;
        int n0 = (st - s * PER) * 8;
        int base = s * 48;
        float acc[3][4] = {};
#pragma unroll
        for (int j = 0; j < 3; j++) {
            uint32_t B[2];
            const __half* bp = hs + offH + (base + j * 16 + 2 * lc) * LDH + n0 + lr;
            B[0] = pack16(bp, bp + LDH);
            B[1] = pack16(bp + 8 * LDH, bp + 9 * LDH);
#pragma unroll
            for (int mi = 0; mi < 3; mi++) mma16(acc[mi], Af[mi][j], B);
        }
#pragma unroll
        for (int mi = 0; mi < 3; mi++) {
            __half* op = hs + offH + (base + mi * 16 + lr) * LDH + n0 + 2 * lc;
            st2(op, acc[mi][0], acc[mi][1]);
            st2(op + 8 * LDH, acc[mi][2], acc[mi][3]);
        }
    }
}

__global__ __launch_bounds__(THREADS, 3)
void agcn_fused(const float* __restrict__ x,
                const float* __restrict__ W0, const float* __restrict__ b0,
                const float* __restrict__ g0, const float* __restrict__ be0,
                const float* __restrict__ W1, const float* __restrict__ b1,
                const float* __restrict__ Badj1, const float* __restrict__ g1,
                const float* __restrict__ be1,
                const float* __restrict__ W2, const float* __restrict__ b2,
                const float* __restrict__ Badj2, const float* __restrict__ g2,
                const float* __restrict__ be2,
                const float* __restrict__ Wc, const float* __restrict__ bc,
                float* __restrict__ out, int Ntot) {
    extern __shared__ __align__(16) char smraw[];
    __half* hs = (__half*)smraw;
    float* fs = (float*)smraw;
    const int t = threadIdx.x;
    const int wid = t >> 5, lane = t & 31, lr = lane >> 2, lc = lane & 3;
    const int n0g = blockIdx.x * BATCH;
    const float bnscale = rsqrtf(1.0f + 1e-5f);

    // ---- Phase A: params to SMEM (float); zero adjacency ----
    for (int i = t; i < 64; i += THREADS) fs[PB0 + i] = b0[i];
    for (int i = t; i < 128; i += THREADS) fs[PB1 + i] = b1[i];
    for (int i = t; i < 256; i += THREADS) fs[PB2 + i] = b2[i];
    if (t < 48) {
        bool ok = t < 42;
        fs[PG0 + t]  = ok ? g0[t] * bnscale : 0.f;
        fs[PBE0 + t] = ok ? be0[t] : 0.f;
        fs[PG1 + t]  = ok ? g1[t] * bnscale : 0.f;
        fs[PBE1 + t] = ok ? be1[t] : 0.f;
        fs[PG2 + t]  = ok ? g2[t] * bnscale : 0.f;
        fs[PBE2 + t] = ok ? be2[t] : 0.f;
    }
    for (int i = t; i < (2 * 48 * 48) / 2; i += THREADS)
        *(uint32_t*)(hs + HADJ1 + 2 * i) = 0u;
    __syncthreads();

    // ---- Phase B: softmax adjacencies; x tile; W0 staging ----
    if (t < 96) {
        int mat = t / 48, v = t % 48;
        if (v < 42) {
            const float* Bm = mat ? Badj2 : Badj1;
            __half* arow = hs + (mat ? HADJ2 : HADJ1) + v * ADJLD;
            int hand = v / 21, lv = v % 21;
            unsigned mask = 0;
#pragma unroll
            for (int e = 0; e < 23; e++) {
                if (c_EU[e] == lv) mask |= 1u << c_EV[e];
                if (c_EV[e] == lv) mask |= 1u << c_EU[e];
            }
            float deg = (float)(__popc(mask) + 1 + ((v == 0 || v == 21) ? 1 : 0));
            float inv = 1.0f / deg;
            float mx = -1e30f;
            for (int u = 0; u < 42; u++) {
                float bse = 0.f;
                if (u == v) bse += 1.f;
                if (u / 21 == hand && ((mask >> (u % 21)) & 1u)) bse += 1.f;
                if ((v == 0 && u == 21) || (v == 21 && u == 0)) bse += 1.f;
                mx = fmaxf(mx, bse * inv + Bm[v * 42 + u]);
            }
            float ssum = 0.f;
            for (int u = 0; u < 42; u++) {
                float bse = 0.f;
                if (u == v) bse += 1.f;
                if (u / 21 == hand && ((mask >> (u % 21)) & 1u)) bse += 1.f;
                if ((v == 0 && u == 21) || (v == 21 && u == 0)) bse += 1.f;
                float e = expf(bse * inv + Bm[v * 42 + u] - mx);
                ssum += e;
                arow[u] = __float2half(e);
            }
            float is = 1.0f / ssum;
            for (int u = 0; u < 42; u++)
                arow[u] = __float2half(__half2float(arow[u]) * is);
        }
    }
    {   // x tile (fp32 -> half2), rows s*48+j, stride 72
        const float2* x2 = reinterpret_cast<const float2*>(x);
        for (int i = t; i < BATCH * 1344; i += THREADS) {
            int s = i / 1344, p = i - s * 1344;
            float2 v = make_float2(0.f, 0.f);
            if (n0g + s < Ntot) v = x2[(size_t)(n0g + s) * 1344 + p];
            int j = p >> 5, c = (p & 31) << 1;
            st2(hs + HBUFA + (s * 48 + j) * LD0 + c, v.x, v.y);
        }
        for (int i = t; i < BATCH * 6 * 32; i += THREADS) {   // zero padded rows 42..47
            int s = i / 192, p = i - s * 192;
            *(uint32_t*)(hs + HBUFA + (s * 48 + 42 + p / 32) * LD0 + 2 * (p & 31)) = 0u;
        }
    }
    {   // W0 (64x64) -> HH1 area, stride 72
        const float2* w2p = reinterpret_cast<const float2*>(W0);
        for (int i = t; i < 2048; i += THREADS) {
            float2 v = w2p[i];
            int r = (2 * i) >> 6, c = (2 * i) & 63;
            st2(hs + HH1 + r * LD0 + c, v.x, v.y);
        }
    }
    __syncthreads();

    // ---- Phase C: stage0  h0 = relu(bn(x @ W0^T + b0)) -> BUFB ----
    if (wid < 6) {
        int m0 = (wid % 3) * 32, n0 = (wid / 3) * 32;
        float acc[2][4][4];
        gemm16<64, LD0, LD0>(hs, HBUFA, HH1, m0, n0, lr, lc, acc);
#pragma unroll
        for (int im = 0; im < 2; im++) {
            int r = m0 + im * 16 + lr;
            int v = r % 48, v8 = v + 8;
            float s0 = (v < 42) ? fs[PG0 + v] : 0.f, be = (v < 42) ? fs[PBE0 + v] : 0.f;
            float s8 = (v8 < 42) ? fs[PG0 + v8] : 0.f, be8 = (v8 < 42) ? fs[PBE0 + v8] : 0.f;
#pragma unroll
            for (int in = 0; in < 4; in++) {
                int c0 = n0 + in * 8 + 2 * lc;
                float bb0 = fs[PB0 + c0], bb1 = fs[PB0 + c0 + 1];
                __half* hp = hs + HBUFB + r * LD0 + c0;
                st2(hp, (v < 42) ? fmaxf((acc[im][in][0] + bb0) * s0 + be, 0.f) : 0.f,
                        (v < 42) ? fmaxf((acc[im][in][1] + bb1) * s0 + be, 0.f) : 0.f);
                st2(hp + 8 * LD0,
                    (v8 < 42) ? fmaxf((acc[im][in][2] + bb0) * s8 + be8, 0.f) : 0.f,
                    (v8 < 42) ? fmaxf((acc[im][in][3] + bb1) * s8 + be8, 0.f) : 0.f);
            }
        }
    }
    __syncthreads();

    // ---- Phase D: stage W1 (128x64 -> BUFA) + agg1 in-place on BUFB ----
    {
        const float2* w2p = reinterpret_cast<const float2*>(W1);
        for (int i = t; i < 4096; i += THREADS) {
            float2 v = w2p[i];
            int r = (2 * i) >> 6, c = (2 * i) & 63;
            st2(hs + HBUFA + r * LD0 + c, v.x, v.y);
        }
    }
    agg16<64, LD0>(hs, HBUFB, HADJ1, wid, lr, lc);
    __syncthreads();

    // ---- Phase E: lin1  h1 = relu(bn(agg1 @ W1^T + b1)) -> HH1 ----
    for (int g = wid; g < 12; g += NWARPS) {
        int m0 = (g % 3) * 32, n0 = (g / 3) * 32;
        float acc[2][4][4];
        gemm16<64, LD0, LD0>(hs, HBUFB, HBUFA, m0, n0, lr, lc, acc);
#pragma unroll
        for (int im = 0; im < 2; im++) {
            int r = m0 + im * 16 + lr;
            int v = r % 48, v8 = v + 8;
            float s0 = (v < 42) ? fs[PG1 + v] : 0.f, be = (v < 42) ? fs[PBE1 + v] : 0.f;
            float s8 = (v8 < 42) ? fs[PG1 + v8] : 0.f, be8 = (v8 < 42) ? fs[PBE1 + v8] : 0.f;
#pragma unroll
            for (int in = 0; in < 4; in++) {
                int c0 = n0 + in * 8 + 2 * lc;
                float bb0 = fs[PB1 + c0], bb1 = fs[PB1 + c0 + 1];
                __half* hp = hs + HH1 + r * LD1 + c0;
                st2(hp, (v < 42) ? fmaxf((acc[im][in][0] + bb0) * s0 + be, 0.f) : 0.f,
                        (v < 42) ? fmaxf((acc[im][in][1] + bb1) * s0 + be, 0.f) : 0.f);
                st2(hp + 8 * LD1,
                    (v8 < 42) ? fmaxf((acc[im][in][2] + bb0) * s8 + be8, 0.f) : 0.f,
                    (v8 < 42) ? fmaxf((acc[im][in][3] + bb1) * s8 + be8, 0.f) : 0.f);
            }
        }
    }
    __syncthreads();

    // ---- Phase F: agg2 in-place on HH1 + zero feat (float, in BUFB) ----
    agg16<128, LD1>(hs, HH1, HADJ2, wid, lr, lc);
    float* feat = fs + HBUFB / 2;
    for (int i = t; i < BATCH * 256; i += THREADS) feat[i] = 0.f;
    __syncthreads();

    // ---- Phase G: lin2 in 4 chunks of 64 channels, fused joint-mean ----
    for (int ch = 0; ch < 4; ch++) {
        const float2* w2p = reinterpret_cast<const float2*>(W2 + ch * 64 * 128);
        for (int i = t; i < 4096; i += THREADS) {
            float2 v = w2p[i];
            int r = (2 * i) >> 7, c = (2 * i) & 127;
            st2(hs + HBUFA + r * LD1 + c, v.x, v.y);
        }
        __syncthreads();
        if (wid < 6) {
            int m0 = (wid % 3) * 32, n0 = (wid / 3) * 32;
            float acc[2][4][4];
            gemm16<128, LD1, LD1>(hs, HH1, HBUFA, m0, n0, lr, lc, acc);
#pragma unroll
            for (int im = 0; im < 2; im++) {
                int r = m0 + im * 16 + lr;
                int v = r % 48, v8 = v + 8, s = r / 48;
#pragma unroll
                for (int in = 0; in < 4; in++) {
                    int cg = ch * 64 + n0 + in * 8 + 2 * lc;
                    float bb0 = fs[PB2 + cg], bb1 = fs[PB2 + cg + 1];
                    float add0 = 0.f, add1 = 0.f;
                    if (v < 42) {
                        float sc = fs[PG2 + v], bb = fs[PBE2 + v];
                        add0 += fmaxf((acc[im][in][0] + bb0) * sc + bb, 0.f);
                        add1 += fmaxf((acc[im][in][1] + bb1) * sc + bb, 0.f);
                    }
                    if (v8 < 42) {
                        float sc = fs[PG2 + v8], bb = fs[PBE2 + v8];
                        add0 += fmaxf((acc[im][in][2] + bb0) * sc + bb, 0.f);
                        add1 += fmaxf((acc[im][in][3] + bb1) * sc + bb, 0.f);
                    }
                    if (add0 != 0.f) atomicAdd(&feat[s * 256 + cg], add0);
                    if (add1 != 0.f) atomicAdd(&feat[s * 256 + cg + 1], add1);
                }
            }
        }
        __syncthreads();
    }

    // ---- Phase H: classifier ----
    if (wid < 4) {
        int s = wid >> 1, k = wid & 1;
        const float* wc = Wc + k * 256;
        float sum = 0.f;
        for (int d = lane; d < 256; d += 32) sum += feat[s * 256 + d] * wc[d];
#pragma unroll
        for (int o = 16; o; o >>= 1) sum += __shfl_xor_sync(0xffffffffu, sum, o);
        if (lane == 0 && n0g + s < Ntot)
            out[(n0g + s) * 2 + k] = sum * (1.0f / 42.0f) + bc[k];
    }
}

extern "C" void kernel_launch(void* const* d_in, const int* in_sizes, int n_in,
                              void* d_out, int out_size) {
    const float* x   = (const float*)d_in[0];
    const float* W0  = (const float*)d_in[1];
    const float* b0  = (const float*)d_in[2];
    const float* g0  = (const float*)d_in[3];
    const float* be0 = (const float*)d_in[4];
    const float* W1  = (const float*)d_in[5];
    const float* b1  = (const float*)d_in[6];
    const float* B1  = (const float*)d_in[7];
    const float* g1  = (const float*)d_in[8];
    const float* be1 = (const float*)d_in[9];
    const float* W2  = (const float*)d_in[10];
    const float* b2  = (const float*)d_in[11];
    const float* B2  = (const float*)d_in[12];
    const float* g2  = (const float*)d_in[13];
    const float* be2 = (const float*)d_in[14];
    const float* Wc  = (const float*)d_in[15];
    const float* bc  = (const float*)d_in[16];
    float* out = (float*)d_out;

    int Ntot = in_sizes[0] / (42 * 64);
    int grid = (Ntot + BATCH - 1) / BATCH;

    cudaFuncSetAttribute(agcn_fused, cudaFuncAttributeMaxDynamicSharedMemorySize, SMEM_BYTES);
    agcn_fused<<<grid, THREADS, SMEM_BYTES>>>(x, W0, b0, g0, be0,
                                              W1, b1, B1, g1, be1,
                                              W2, b2, B2, g2, be2,
                                              Wc, bc, out, Ntot);
}